// round 1
// baseline (speedup 1.0000x reference)
#include <cuda_runtime.h>
#include <math_constants.h>

// Problem constants (fixed by the dataset)
#define NG      512     // graphs
#define N_PER   256     // nodes per graph
#define DD      128     // embed dim
#define E_PER   4096    // edges per graph
#define KK      128     // kept nodes per graph
#define THREADS 512

struct Smem {
    float x[N_PER * DD];   // 131072 B : the graph's x tile
    int   src[E_PER];      // 16384 B  : local src ids
    int   dst[E_PER];      // 16384 B  : local dst ids
    float w[DD];           // gcn weight
    float xw[N_PER];       // x @ gcn_w
    float dinv[N_PER];     // rsqrt(deg)
    float agg[N_PER];      // score accumulator, then score
    float gate[N_PER];     // tanh(score)
    int   itmp[N_PER];     // deg, then keep flag
    float readout[2 * DD]; // [mean | max]
    float psum[4][DD];     // pooling / gemm partials
    float pmax[4][DD];
};

__global__ void __launch_bounds__(THREADS, 1)
sagpool_fused_kernel(const float* __restrict__ x,
                     const int*   __restrict__ edge_index,
                     const float* __restrict__ gcn_w,
                     const float* __restrict__ gcn_b,
                     const float* __restrict__ lin_w,
                     const float* __restrict__ lin_b,
                     float*       __restrict__ out,
                     int E_total)
{
    extern __shared__ unsigned char smem_raw[];
    Smem* s = reinterpret_cast<Smem*>(smem_raw);

    const int g   = blockIdx.x;
    const int tid = threadIdx.x;

    // ---- Stage x tile (128 KB) into shared, float4-vectorized ----
    const float4* xg4 = reinterpret_cast<const float4*>(x + (size_t)g * N_PER * DD);
    float4* xs4 = reinterpret_cast<float4*>(s->x);
    #pragma unroll
    for (int i = tid; i < N_PER * DD / 4; i += THREADS)
        xs4[i] = xg4[i];

    // ---- Stage edges (local ids; node base is g*256, so &255 works) ----
    const int* srcg = edge_index + (size_t)g * E_PER;
    const int* dstg = edge_index + (size_t)E_total + (size_t)g * E_PER;
    #pragma unroll
    for (int i = tid; i < E_PER; i += THREADS) {
        s->src[i] = srcg[i] & (N_PER - 1);
        s->dst[i] = dstg[i] & (N_PER - 1);
    }

    if (tid < DD)    s->w[tid]    = gcn_w[tid];
    if (tid < N_PER) s->itmp[tid] = 1;   // degree init (self-loop)
    __syncthreads();

    // ---- Degree count (shared int atomics) ----
    #pragma unroll
    for (int i = tid; i < E_PER; i += THREADS)
        atomicAdd(&s->itmp[s->dst[i]], 1);

    // ---- xw = x @ gcn_w : one warp per node, float4 + warp reduce ----
    {
        const int wid  = tid >> 5;
        const int lane = tid & 31;
        const float4 wv = reinterpret_cast<const float4*>(s->w)[lane];
        #pragma unroll
        for (int i = 0; i < N_PER / 16; ++i) {
            const int node = wid * (N_PER / 16) + i;
            const float4 v = reinterpret_cast<const float4*>(s->x + node * DD)[lane];
            float d = v.x * wv.x + v.y * wv.y + v.z * wv.z + v.w * wv.w;
            #pragma unroll
            for (int off = 16; off; off >>= 1)
                d += __shfl_down_sync(0xFFFFFFFFu, d, off);
            if (lane == 0) s->xw[node] = d;
        }
    }
    __syncthreads();

    // ---- dinv + self-loop contribution ----
    if (tid < N_PER) {
        const float dv = rsqrtf((float)s->itmp[tid]);
        s->dinv[tid] = dv;
        s->agg[tid]  = s->xw[tid] * dv * dv;
    }
    __syncthreads();

    // ---- Edge messages: agg[dst] += xw[src] * dinv[src] * dinv[dst] ----
    #pragma unroll
    for (int i = tid; i < E_PER; i += THREADS) {
        const int a = s->src[i];
        const int b = s->dst[i];
        atomicAdd(&s->agg[b], s->xw[a] * s->dinv[a] * s->dinv[b]);
    }
    __syncthreads();

    // ---- score + gate ----
    const float bias0 = gcn_b[0];
    if (tid < N_PER) {
        const float sc = s->agg[tid] + bias0;
        s->agg[tid]  = sc;
        s->gate[tid] = tanhf(sc);
    }
    __syncthreads();

    // ---- top-K by rank counting (stable: ties broken by lower index) ----
    if (tid < N_PER) {
        const float si = s->agg[tid];
        int cnt = 0;
        #pragma unroll 8
        for (int j = 0; j < N_PER; ++j) {
            const float sj = s->agg[j];
            cnt += (sj > si) || (sj == si && j < tid);
        }
        s->itmp[tid] = (cnt < KK) ? 1 : 0;
    }
    __syncthreads();

    // ---- gated mean/max pooling over kept nodes (deterministic order) ----
    const int q = tid >> 7;     // 0..3
    const int d = tid & (DD - 1);
    {
        float sum = 0.0f, mx = -CUDART_INF_F;
        for (int n = q; n < N_PER; n += 4) {
            if (s->itmp[n]) {
                const float v = s->x[n * DD + d] * s->gate[n];
                sum += v;
                mx = fmaxf(mx, v);
            }
        }
        s->psum[q][d] = sum;
        s->pmax[q][d] = mx;
    }
    __syncthreads();
    if (tid < DD) {
        const float ss = s->psum[0][tid] + s->psum[1][tid] + s->psum[2][tid] + s->psum[3][tid];
        const float mm = fmaxf(fmaxf(s->pmax[0][tid], s->pmax[1][tid]),
                               fmaxf(s->pmax[2][tid], s->pmax[3][tid]));
        s->readout[tid]      = ss * (1.0f / (float)KK);
        s->readout[DD + tid] = mm;
    }
    __syncthreads();

    // ---- final GEMM row: out[g,:] = readout @ lin_w + lin_b ----
    {
        float acc = 0.0f;
        const int k0 = q * (2 * DD / 4);
        #pragma unroll 16
        for (int k = k0; k < k0 + (2 * DD / 4); ++k)
            acc = fmaf(s->readout[k], lin_w[k * DD + d], acc);
        s->psum[q][d] = acc;
    }
    __syncthreads();
    if (tid < DD) {
        const float o = s->psum[0][tid] + s->psum[1][tid] +
                        s->psum[2][tid] + s->psum[3][tid] + lin_b[tid];
        out[g * DD + tid] = o;
    }
}

extern "C" void kernel_launch(void* const* d_in, const int* in_sizes, int n_in,
                              void* d_out, int out_size)
{
    const float* x        = (const float*)d_in[0];  // [N, D]
    // d_in[1] = graph_indicator (unused; graphs are equal-size & contiguous)
    const int*   ei       = (const int*)  d_in[2];  // [2, E]
    const float* gcn_w    = (const float*)d_in[3];  // [D, 1]
    const float* gcn_b    = (const float*)d_in[4];  // [1]
    const float* lin_w    = (const float*)d_in[5];  // [2D, D]
    const float* lin_b    = (const float*)d_in[6];  // [D]
    float*       out      = (float*)d_out;          // [G, D]

    const int E_total = in_sizes[2] / 2;

    static bool attr_set = false;
    // Idempotent attribute set each call (cheap, not a stream op, capture-safe).
    cudaFuncSetAttribute(sagpool_fused_kernel,
                         cudaFuncAttributeMaxDynamicSharedMemorySize,
                         (int)sizeof(Smem));
    (void)attr_set;

    sagpool_fused_kernel<<<NG, THREADS, sizeof(Smem)>>>(
        x, ei, gcn_w, gcn_b, lin_w, lin_b, out, E_total);
}

// round 2
// speedup vs baseline: 1.2826x; 1.2826x over previous
#include <cuda_runtime.h>
#include <math_constants.h>

// Problem constants (fixed by the dataset)
#define NG      512     // graphs
#define N_PER   256     // nodes per graph
#define DD      128     // embed dim
#define E_PER   4096    // edges per graph
#define KK      128     // kept nodes per graph
#define T1      256     // threads, kernel 1
#define T2      256     // threads, kernel 2
#define G_PER_B2 8      // graphs per block, kernel 2

// Scratch: readout [G, 2D]  (mean | max)
__device__ float g_readout[NG * 2 * DD];

// ---------------------------------------------------------------------------
// Kernel 1: per-graph score -> topk -> gated mean/max readout
// ---------------------------------------------------------------------------
__global__ void __launch_bounds__(T1, 4)
sagpool_readout_kernel(const float* __restrict__ x,
                       const int*   __restrict__ edge_index,
                       const float* __restrict__ gcn_w,
                       const float* __restrict__ gcn_b,
                       int E_total)
{
    __shared__ unsigned short s_src[E_PER];
    __shared__ unsigned short s_dst[E_PER];
    __shared__ float s_xw[N_PER];
    __shared__ float s_dinv[N_PER];
    __shared__ float s_agg[N_PER];
    __shared__ float s_gate[N_PER];
    __shared__ int   s_flag[N_PER];       // degree, then keep flag
    __shared__ float s_psum[2][DD];
    __shared__ float s_pmax[2][DD];

    const int g    = blockIdx.x;
    const int tid  = threadIdx.x;
    const int wid  = tid >> 5;
    const int lane = tid & 31;

    if (tid < N_PER) s_flag[tid] = 1;     // self-loop degree
    __syncthreads();

    // ---- Stage edges as local ids + degree count ----
    const int* srcg = edge_index + (size_t)g * E_PER;
    const int* dstg = edge_index + (size_t)E_total + (size_t)g * E_PER;
    #pragma unroll
    for (int i = tid; i < E_PER; i += T1) {
        const int a = srcg[i] & (N_PER - 1);
        const int b = dstg[i] & (N_PER - 1);
        s_src[i] = (unsigned short)a;
        s_dst[i] = (unsigned short)b;
        atomicAdd(&s_flag[b], 1);
    }

    // ---- xw = x @ gcn_w : warp-cooperative, streamed from global ----
    {
        const float4 wv = reinterpret_cast<const float4*>(gcn_w)[lane];
        const float4* xg = reinterpret_cast<const float4*>(x + (size_t)g * N_PER * DD);
        #pragma unroll 4
        for (int i = 0; i < N_PER / 8; ++i) {             // 8 warps, 32 nodes each
            const int node = wid * (N_PER / 8) + i;
            const float4 v = xg[node * (DD / 4) + lane];
            float d = v.x * wv.x + v.y * wv.y + v.z * wv.z + v.w * wv.w;
            #pragma unroll
            for (int off = 16; off; off >>= 1)
                d += __shfl_down_sync(0xFFFFFFFFu, d, off);
            if (lane == 0) s_xw[node] = d;
        }
    }
    __syncthreads();

    // ---- dinv + self-loop contribution ----
    if (tid < N_PER) {
        const float dv = rsqrtf((float)s_flag[tid]);
        const float xd = s_xw[tid] * dv;
        s_dinv[tid] = dv;
        s_xw[tid]   = xd;                 // pre-scale: xw*dinv(src)
        s_agg[tid]  = xd * dv;            // self-loop term
    }
    __syncthreads();

    // ---- Edge messages: agg[dst] += xw[src]*dinv[src] * dinv[dst] ----
    #pragma unroll
    for (int i = tid; i < E_PER; i += T1) {
        const int a = s_src[i];
        const int b = s_dst[i];
        atomicAdd(&s_agg[b], s_xw[a] * s_dinv[b]);
    }
    __syncthreads();

    // ---- score + gate ----
    const float bias0 = __ldg(gcn_b);
    if (tid < N_PER) {
        const float sc = s_agg[tid] + bias0;
        s_agg[tid]  = sc;
        s_gate[tid] = tanhf(sc);
    }
    __syncthreads();

    // ---- top-K by rank counting (stable, matches lax.top_k tie-break) ----
    if (tid < N_PER) {
        const float si = s_agg[tid];
        int cnt = 0;
        #pragma unroll 8
        for (int j = 0; j < N_PER; ++j) {
            const float sj = s_agg[j];
            cnt += (sj > si) || (sj == si && j < tid);
        }
        s_flag[tid] = (cnt < KK) ? 1 : 0;
    }
    __syncthreads();

    // ---- gated mean/max pooling; x re-read from global (L2-resident) ----
    {
        const int q = tid >> 7;           // 0..1
        const int d = tid & (DD - 1);
        const float* xr = x + (size_t)g * N_PER * DD + d;
        float sum = 0.0f, mx = -CUDART_INF_F;
        #pragma unroll 4
        for (int n = q; n < N_PER; n += 2) {
            const float gt = s_gate[n];
            const int   kp = s_flag[n];
            const float v  = xr[n * DD] * gt;
            if (kp) { sum += v; mx = fmaxf(mx, v); }
        }
        s_psum[q][d] = sum;
        s_pmax[q][d] = mx;
    }
    __syncthreads();
    if (tid < DD) {
        g_readout[g * (2 * DD) + tid]      = (s_psum[0][tid] + s_psum[1][tid]) * (1.0f / (float)KK);
        g_readout[g * (2 * DD) + DD + tid] = fmaxf(s_pmax[0][tid], s_pmax[1][tid]);
    }
}

// ---------------------------------------------------------------------------
// Kernel 2: out[G,D] = readout[G,2D] @ lin_w[2D,D] + lin_b
// ---------------------------------------------------------------------------
__global__ void __launch_bounds__(T2, 4)
sagpool_linear_kernel(const float* __restrict__ lin_w,
                      const float* __restrict__ lin_b,
                      float*       __restrict__ out)
{
    __shared__ float s_ro[G_PER_B2][2 * DD];   // 8 KB

    const int tid = threadIdx.x;
    const int g0  = blockIdx.x * G_PER_B2;

    // stage readout tile (coalesced)
    #pragma unroll
    for (int i = tid; i < G_PER_B2 * 2 * DD; i += T2)
        s_ro[i / (2 * DD)][i % (2 * DD)] = g_readout[g0 * (2 * DD) + i];
    __syncthreads();

    const int d = tid & (DD - 1);
    const int h = tid >> 7;                    // 0..1 -> rows h*4..h*4+3
    const int r0 = h * (G_PER_B2 / 2);

    float acc0 = 0.f, acc1 = 0.f, acc2 = 0.f, acc3 = 0.f;
    #pragma unroll 8
    for (int k = 0; k < 2 * DD; ++k) {
        const float wv = lin_w[k * DD + d];    // coalesced; L2-hot after 1st block
        acc0 = fmaf(s_ro[r0 + 0][k], wv, acc0);
        acc1 = fmaf(s_ro[r0 + 1][k], wv, acc1);
        acc2 = fmaf(s_ro[r0 + 2][k], wv, acc2);
        acc3 = fmaf(s_ro[r0 + 3][k], wv, acc3);
    }
    const float b = lin_b[d];
    out[(g0 + r0 + 0) * DD + d] = acc0 + b;
    out[(g0 + r0 + 1) * DD + d] = acc1 + b;
    out[(g0 + r0 + 2) * DD + d] = acc2 + b;
    out[(g0 + r0 + 3) * DD + d] = acc3 + b;
}

// ---------------------------------------------------------------------------
extern "C" void kernel_launch(void* const* d_in, const int* in_sizes, int n_in,
                              void* d_out, int out_size)
{
    const float* x     = (const float*)d_in[0];  // [N, D]
    // d_in[1] = graph_indicator (unused; equal-size contiguous graphs)
    const int*   ei    = (const int*)  d_in[2];  // [2, E]
    const float* gcn_w = (const float*)d_in[3];  // [D, 1]
    const float* gcn_b = (const float*)d_in[4];  // [1]
    const float* lin_w = (const float*)d_in[5];  // [2D, D]
    const float* lin_b = (const float*)d_in[6];  // [D]
    float*       out   = (float*)d_out;          // [G, D]

    const int E_total = in_sizes[2] / 2;

    sagpool_readout_kernel<<<NG, T1>>>(x, ei, gcn_w, gcn_b, E_total);
    sagpool_linear_kernel<<<NG / G_PER_B2, T2>>>(lin_w, lin_b, out);
}

// round 3
// speedup vs baseline: 1.4056x; 1.0960x over previous
#include <cuda_runtime.h>
#include <math_constants.h>

// Problem constants (fixed by the dataset)
#define NG      512     // graphs
#define N_PER   256     // nodes per graph
#define DD      128     // embed dim
#define E_PER   4096    // edges per graph
#define KK      128     // kept nodes per graph
#define T1      256     // threads, kernel 1
#define T2      256     // threads, kernel 2
#define G_PER_B2 4      // graphs per block, kernel 2

// Scratch: readout [G, 2D]  (mean | max)
__device__ float g_readout[NG * 2 * DD];

// ---------------------------------------------------------------------------
// Kernel 1: per-graph score -> topk -> gated mean/max readout
// ---------------------------------------------------------------------------
__global__ void __launch_bounds__(T1, 4)
sagpool_readout_kernel(const float* __restrict__ x,
                       const int*   __restrict__ edge_index,
                       const float* __restrict__ gcn_w,
                       const float* __restrict__ gcn_b,
                       int E_total)
{
    __shared__ unsigned short s_src[E_PER];
    __shared__ unsigned short s_dst[E_PER];
    __shared__ float s_xw[N_PER];
    __shared__ float s_dinv[N_PER];
    __shared__ float s_agg[N_PER];
    __shared__ float s_gate[N_PER];
    __shared__ int   s_flag[N_PER];        // degree, then keep flag
    __shared__ float4 s_psum4[8][DD / 4];  // 4 KB
    __shared__ float4 s_pmax4[8][DD / 4];  // 4 KB

    const int g    = blockIdx.x;
    const int tid  = threadIdx.x;
    const int wid  = tid >> 5;
    const int lane = tid & 31;

    if (tid < N_PER) s_flag[tid] = 1;      // self-loop degree
    __syncthreads();

    // ---- Stage edges as local ids + degree count ----
    const int* srcg = edge_index + (size_t)g * E_PER;
    const int* dstg = edge_index + (size_t)E_total + (size_t)g * E_PER;
    #pragma unroll
    for (int i = tid; i < E_PER; i += T1) {
        const int a = srcg[i] & (N_PER - 1);
        const int b = dstg[i] & (N_PER - 1);
        s_src[i] = (unsigned short)a;
        s_dst[i] = (unsigned short)b;
        atomicAdd(&s_flag[b], 1);
    }

    // ---- xw = x @ gcn_w : warp-cooperative, streamed from global ----
    {
        const float4 wv = reinterpret_cast<const float4*>(gcn_w)[lane];
        const float4* xg = reinterpret_cast<const float4*>(x + (size_t)g * N_PER * DD);
        #pragma unroll 4
        for (int i = 0; i < N_PER / 8; ++i) {              // 8 warps, 32 nodes each
            const int node = wid * (N_PER / 8) + i;
            const float4 v = xg[node * (DD / 4) + lane];
            float d = v.x * wv.x + v.y * wv.y + v.z * wv.z + v.w * wv.w;
            #pragma unroll
            for (int off = 16; off; off >>= 1)
                d += __shfl_down_sync(0xFFFFFFFFu, d, off);
            if (lane == 0) s_xw[node] = d;
        }
    }
    __syncthreads();

    // ---- dinv + self-loop contribution ----
    if (tid < N_PER) {
        const float dv = rsqrtf((float)s_flag[tid]);
        const float xd = s_xw[tid] * dv;
        s_dinv[tid] = dv;
        s_xw[tid]   = xd;                  // pre-scaled: xw*dinv(src)
        s_agg[tid]  = xd * dv;             // self-loop term
    }
    __syncthreads();

    // ---- Edge messages: agg[dst] += xw[src]*dinv[src] * dinv[dst] ----
    #pragma unroll
    for (int i = tid; i < E_PER; i += T1) {
        const int a = s_src[i];
        const int b = s_dst[i];
        atomicAdd(&s_agg[b], s_xw[a] * s_dinv[b]);
    }
    __syncthreads();

    // ---- score + gate ----
    const float bias0 = __ldg(gcn_b);
    if (tid < N_PER) {
        const float sc = s_agg[tid] + bias0;
        s_agg[tid]  = sc;
        s_gate[tid] = tanhf(sc);
    }
    __syncthreads();

    // ---- top-K by rank counting (stable, matches lax.top_k tie-break) ----
    if (tid < N_PER) {
        const float si = s_agg[tid];
        int cnt = 0;
        #pragma unroll 8
        for (int j = 0; j < N_PER; ++j) {
            const float sj = s_agg[j];
            cnt += (sj > si) || (sj == si && j < tid);
        }
        s_flag[tid] = (cnt < KK) ? 1 : 0;
    }
    __syncthreads();

    // ---- gated mean/max pooling (float4, 8-way node split); x from L2 ----
    {
        const int q  = tid >> 5;           // 0..7
        const int d4 = tid & 31;           // float4 lane -> covers 128 floats
        const float4* xr = reinterpret_cast<const float4*>(x + (size_t)g * N_PER * DD) + d4;
        float4 sum = make_float4(0.f, 0.f, 0.f, 0.f);
        float4 mx  = make_float4(-CUDART_INF_F, -CUDART_INF_F, -CUDART_INF_F, -CUDART_INF_F);
        #pragma unroll 4
        for (int n = q; n < N_PER; n += 8) {
            if (s_flag[n]) {
                const float gt = s_gate[n];
                const float4 v = xr[n * (DD / 4)];
                const float vx = v.x * gt, vy = v.y * gt, vz = v.z * gt, vw = v.w * gt;
                sum.x += vx; sum.y += vy; sum.z += vz; sum.w += vw;
                mx.x = fmaxf(mx.x, vx); mx.y = fmaxf(mx.y, vy);
                mx.z = fmaxf(mx.z, vz); mx.w = fmaxf(mx.w, vw);
            }
        }
        s_psum4[q][d4] = sum;
        s_pmax4[q][d4] = mx;
    }
    __syncthreads();
    if (tid < 32) {
        float4 a = s_psum4[0][tid];
        #pragma unroll
        for (int q = 1; q < 8; ++q) {
            const float4 b = s_psum4[q][tid];
            a.x += b.x; a.y += b.y; a.z += b.z; a.w += b.w;
        }
        const float inv = 1.0f / (float)KK;
        a.x *= inv; a.y *= inv; a.z *= inv; a.w *= inv;
        reinterpret_cast<float4*>(g_readout + g * (2 * DD))[tid] = a;
    } else if (tid < 64) {
        const int t = tid - 32;
        float4 a = s_pmax4[0][t];
        #pragma unroll
        for (int q = 1; q < 8; ++q) {
            const float4 b = s_pmax4[q][t];
            a.x = fmaxf(a.x, b.x); a.y = fmaxf(a.y, b.y);
            a.z = fmaxf(a.z, b.z); a.w = fmaxf(a.w, b.w);
        }
        reinterpret_cast<float4*>(g_readout + g * (2 * DD) + DD)[t] = a;
    }
}

// ---------------------------------------------------------------------------
// Kernel 2: out[G,D] = readout[G,2D] @ lin_w[2D,D] + lin_b
//   grid = 128 blocks x 4 graphs, split-k over two thread-halves
// ---------------------------------------------------------------------------
__global__ void __launch_bounds__(T2, 8)
sagpool_linear_kernel(const float* __restrict__ lin_w,
                      const float* __restrict__ lin_b,
                      float*       __restrict__ out)
{
    __shared__ float s_ro[G_PER_B2][2 * DD];   // 4 KB
    __shared__ float s_part[G_PER_B2][DD];     // 2 KB (h==1 partials)

    const int tid = threadIdx.x;
    const int g0  = blockIdx.x * G_PER_B2;

    // stage readout tile (coalesced)
    #pragma unroll
    for (int i = tid; i < G_PER_B2 * 2 * DD; i += T2)
        s_ro[i / (2 * DD)][i % (2 * DD)] = g_readout[g0 * (2 * DD) + i];
    __syncthreads();

    const int d = tid & (DD - 1);
    const int h = tid >> 7;                    // k-half: 0 or 1

    float acc0 = 0.f, acc1 = 0.f, acc2 = 0.f, acc3 = 0.f;
    const float* wp = lin_w + h * DD * DD + d;
    const float* r0 = &s_ro[0][h * DD];
    const float* r1 = &s_ro[1][h * DD];
    const float* r2 = &s_ro[2][h * DD];
    const float* r3 = &s_ro[3][h * DD];
    #pragma unroll 8
    for (int k = 0; k < DD; ++k) {
        const float wv = wp[k * DD];           // coalesced; L2-hot after 1st wave
        acc0 = fmaf(r0[k], wv, acc0);
        acc1 = fmaf(r1[k], wv, acc1);
        acc2 = fmaf(r2[k], wv, acc2);
        acc3 = fmaf(r3[k], wv, acc3);
    }
    if (h == 1) {
        s_part[0][d] = acc0;
        s_part[1][d] = acc1;
        s_part[2][d] = acc2;
        s_part[3][d] = acc3;
    }
    __syncthreads();
    if (h == 0) {
        const float b = lin_b[d];
        out[(g0 + 0) * DD + d] = acc0 + s_part[0][d] + b;
        out[(g0 + 1) * DD + d] = acc1 + s_part[1][d] + b;
        out[(g0 + 2) * DD + d] = acc2 + s_part[2][d] + b;
        out[(g0 + 3) * DD + d] = acc3 + s_part[3][d] + b;
    }
}

// ---------------------------------------------------------------------------
extern "C" void kernel_launch(void* const* d_in, const int* in_sizes, int n_in,
                              void* d_out, int out_size)
{
    const float* x     = (const float*)d_in[0];  // [N, D]
    // d_in[1] = graph_indicator (unused; equal-size contiguous graphs)
    const int*   ei    = (const int*)  d_in[2];  // [2, E]
    const float* gcn_w = (const float*)d_in[3];  // [D, 1]
    const float* gcn_b = (const float*)d_in[4];  // [1]
    const float* lin_w = (const float*)d_in[5];  // [2D, D]
    const float* lin_b = (const float*)d_in[6];  // [D]
    float*       out   = (float*)d_out;          // [G, D]

    const int E_total = in_sizes[2] / 2;

    sagpool_readout_kernel<<<NG, T1>>>(x, ei, gcn_w, gcn_b, E_total);
    sagpool_linear_kernel<<<NG / G_PER_B2, T2>>>(lin_w, lin_b, out);
}

// round 4
// speedup vs baseline: 1.5632x; 1.1121x over previous
#include <cuda_runtime.h>
#include <math_constants.h>

// Problem constants (fixed by the dataset)
#define NG      512     // graphs
#define N_PER   256     // nodes per graph
#define DD      128     // embed dim
#define E_PER   4096    // edges per graph
#define KK      128     // kept nodes per graph
#define T1      256     // threads per CTA

// ---------------------------------------------------------------------------
// Fully fused: per-graph score -> topk -> gated mean/max readout -> linear
// One CTA per graph, 512 CTAs (~3.5 per SM) so phases overlap across CTAs.
// ---------------------------------------------------------------------------
__global__ void __launch_bounds__(T1, 4)
sagpool_fused_kernel(const float* __restrict__ x,
                     const int*   __restrict__ edge_index,
                     const float* __restrict__ gcn_w,
                     const float* __restrict__ gcn_b,
                     const float* __restrict__ lin_w,
                     const float* __restrict__ lin_b,
                     float*       __restrict__ out,
                     int E_total)
{
    __shared__ unsigned short s_src[E_PER];   // 8 KB
    __shared__ unsigned short s_dst[E_PER];   // 8 KB
    __shared__ float s_xw[N_PER];
    __shared__ float s_dinv[N_PER];
    __shared__ float s_agg[N_PER];
    __shared__ float s_gate[N_PER];
    __shared__ int   s_flag[N_PER];           // degree, then keep flag
    __shared__ float4 s_psum4[8][DD / 4];     // 4 KB
    __shared__ float4 s_pmax4[8][DD / 4];     // 4 KB
    __shared__ float s_read[2 * DD];          // readout [mean | max]
    __shared__ float s_part[DD];              // epilogue split-k partial

    const int g    = blockIdx.x;
    const int tid  = threadIdx.x;
    const int wid  = tid >> 5;
    const int lane = tid & 31;

    if (tid < N_PER) s_flag[tid] = 1;         // self-loop degree
    __syncthreads();

    // ---- Stage edges as local ids + degree count (shared atomics) ----
    const int* srcg = edge_index + (size_t)g * E_PER;
    const int* dstg = edge_index + (size_t)E_total + (size_t)g * E_PER;
    #pragma unroll
    for (int i = tid; i < E_PER; i += T1) {
        const int a = srcg[i] & (N_PER - 1);
        const int b = dstg[i] & (N_PER - 1);
        s_src[i] = (unsigned short)a;
        s_dst[i] = (unsigned short)b;
        atomicAdd(&s_flag[b], 1);
    }

    // ---- xw = x @ gcn_w : warp-cooperative, streamed from global ----
    {
        const float4 wv = reinterpret_cast<const float4*>(gcn_w)[lane];
        const float4* xg = reinterpret_cast<const float4*>(x + (size_t)g * N_PER * DD);
        #pragma unroll 4
        for (int i = 0; i < N_PER / 8; ++i) {              // 8 warps, 32 nodes each
            const int node = wid * (N_PER / 8) + i;
            const float4 v = xg[node * (DD / 4) + lane];
            float d = v.x * wv.x + v.y * wv.y + v.z * wv.z + v.w * wv.w;
            #pragma unroll
            for (int off = 16; off; off >>= 1)
                d += __shfl_down_sync(0xFFFFFFFFu, d, off);
            if (lane == 0) s_xw[node] = d;
        }
    }
    __syncthreads();

    // ---- dinv + self-loop contribution ----
    if (tid < N_PER) {
        const float dv = rsqrtf((float)s_flag[tid]);
        const float xd = s_xw[tid] * dv;
        s_dinv[tid] = dv;
        s_xw[tid]   = xd;                  // pre-scaled: xw*dinv(src)
        s_agg[tid]  = xd * dv;             // self-loop term
    }
    __syncthreads();

    // ---- Edge messages: agg[dst] += xw[src]*dinv[src] * dinv[dst] ----
    #pragma unroll
    for (int i = tid; i < E_PER; i += T1) {
        const int a = s_src[i];
        const int b = s_dst[i];
        atomicAdd(&s_agg[b], s_xw[a] * s_dinv[b]);
    }
    __syncthreads();

    // ---- score + gate ----
    const float bias0 = __ldg(gcn_b);
    if (tid < N_PER) {
        const float sc = s_agg[tid] + bias0;
        s_agg[tid]  = sc;
        s_gate[tid] = tanhf(sc);
    }
    __syncthreads();

    // ---- top-K by rank counting (stable, matches lax.top_k tie-break) ----
    if (tid < N_PER) {
        const float si = s_agg[tid];
        int cnt = 0;
        #pragma unroll 8
        for (int j = 0; j < N_PER; ++j) {
            const float sj = s_agg[j];
            cnt += (sj > si) || (sj == si && j < tid);
        }
        s_flag[tid] = (cnt < KK) ? 1 : 0;
    }
    __syncthreads();

    // ---- gated mean/max pooling (float4, 8-way node split); x from L2 ----
    {
        const int q  = tid >> 5;           // 0..7
        const int d4 = tid & 31;           // float4 lane -> covers 128 floats
        const float4* xr = reinterpret_cast<const float4*>(x + (size_t)g * N_PER * DD) + d4;
        float4 sum = make_float4(0.f, 0.f, 0.f, 0.f);
        float4 mx  = make_float4(-CUDART_INF_F, -CUDART_INF_F, -CUDART_INF_F, -CUDART_INF_F);
        #pragma unroll 4
        for (int n = q; n < N_PER; n += 8) {
            if (s_flag[n]) {
                const float gt = s_gate[n];
                const float4 v = xr[n * (DD / 4)];
                const float vx = v.x * gt, vy = v.y * gt, vz = v.z * gt, vw = v.w * gt;
                sum.x += vx; sum.y += vy; sum.z += vz; sum.w += vw;
                mx.x = fmaxf(mx.x, vx); mx.y = fmaxf(mx.y, vy);
                mx.z = fmaxf(mx.z, vz); mx.w = fmaxf(mx.w, vw);
            }
        }
        s_psum4[q][d4] = sum;
        s_pmax4[q][d4] = mx;
    }
    __syncthreads();

    // ---- reduce pooling partials into readout [mean | max] ----
    if (tid < 32) {
        float4 a = s_psum4[0][tid];
        #pragma unroll
        for (int q = 1; q < 8; ++q) {
            const float4 b = s_psum4[q][tid];
            a.x += b.x; a.y += b.y; a.z += b.z; a.w += b.w;
        }
        const float inv = 1.0f / (float)KK;
        a.x *= inv; a.y *= inv; a.z *= inv; a.w *= inv;
        reinterpret_cast<float4*>(s_read)[tid] = a;
    } else if (tid < 64) {
        const int t = tid - 32;
        float4 a = s_pmax4[0][t];
        #pragma unroll
        for (int q = 1; q < 8; ++q) {
            const float4 b = s_pmax4[q][t];
            a.x = fmaxf(a.x, b.x); a.y = fmaxf(a.y, b.y);
            a.z = fmaxf(a.z, b.z); a.w = fmaxf(a.w, b.w);
        }
        reinterpret_cast<float4*>(s_read + DD)[t] = a;
    }
    __syncthreads();

    // ---- fused linear epilogue: out[g,:] = readout @ lin_w + lin_b ----
    // split-k=2 across thread halves; lin_w is L1/L2-hot chip-wide.
    {
        const int d = tid & (DD - 1);
        const int h = tid >> 7;
        const float* wp = lin_w + h * DD * DD + d;
        const float* rp = s_read + h * DD;
        float acc = 0.0f;
        #pragma unroll 8
        for (int k = 0; k < DD; ++k)
            acc = fmaf(rp[k], __ldg(wp + k * DD), acc);
        if (h == 1) s_part[d] = acc;
        __syncthreads();
        if (h == 0)
            out[g * DD + d] = acc + s_part[d] + __ldg(lin_b + d);
    }
}

// ---------------------------------------------------------------------------
extern "C" void kernel_launch(void* const* d_in, const int* in_sizes, int n_in,
                              void* d_out, int out_size)
{
    const float* x     = (const float*)d_in[0];  // [N, D]
    // d_in[1] = graph_indicator (unused; equal-size contiguous graphs)
    const int*   ei    = (const int*)  d_in[2];  // [2, E]
    const float* gcn_w = (const float*)d_in[3];  // [D, 1]
    const float* gcn_b = (const float*)d_in[4];  // [1]
    const float* lin_w = (const float*)d_in[5];  // [2D, D]
    const float* lin_b = (const float*)d_in[6];  // [D]
    float*       out   = (float*)d_out;          // [G, D]

    const int E_total = in_sizes[2] / 2;

    sagpool_fused_kernel<<<NG, T1>>>(x, ei, gcn_w, gcn_b, lin_w, lin_b, out, E_total);
}

// round 5
// speedup vs baseline: 1.6808x; 1.0752x over previous
#include <cuda_runtime.h>
#include <math_constants.h>

// Problem constants (fixed by the dataset)
#define NG      512     // graphs
#define N_PER   256     // nodes per graph
#define DD      128     // embed dim
#define E_PER   4096    // edges per graph
#define KK      128     // kept nodes per graph
#define T1      256     // threads per CTA
#define MAXB    48      // bucket capacity (max in-degree supported w/o overflow)
#define BSTR    50      // bucket row stride in ushorts (25 words, coprime w/ 32 banks)
#define OVF_CAP 256     // overflow edge list capacity

// ---------------------------------------------------------------------------
// Fully fused: per-graph score -> topk -> gated mean/max readout -> linear.
// One CTA per graph; all 512 CTAs resident (4/SM). Edge aggregation uses a
// one-pass bucket scatter (single atomic per edge) + atomic-free gather.
// ---------------------------------------------------------------------------
__global__ void __launch_bounds__(T1, 4)
sagpool_fused_kernel(const float* __restrict__ x,
                     const int*   __restrict__ edge_index,
                     const float* __restrict__ gcn_w,
                     const float* __restrict__ gcn_b,
                     const float* __restrict__ lin_w,
                     const float* __restrict__ lin_b,
                     float*       __restrict__ out,
                     int E_total)
{
    __shared__ unsigned short s_bkt[N_PER * BSTR];  // 25.6 KB CSR buckets (src ids)
    __shared__ int   s_cnt[N_PER];                  // in-degree / cursor
    __shared__ float s_xwp[N_PER];                  // xw, then xw*dinv
    __shared__ float s_dinv[N_PER];
    __shared__ float s_agg[N_PER];                  // edge sum, then score
    __shared__ float s_gate[N_PER];
    __shared__ int   s_flag[N_PER];                 // keep flag
    __shared__ float4 s_psum4[8][DD / 4];           // 4 KB
    __shared__ float4 s_pmax4[8][DD / 4];           // 4 KB
    __shared__ float s_read[2 * DD];
    __shared__ float s_part[DD];
    __shared__ int   s_ovf[OVF_CAP];                // packed (dst<<16)|src
    __shared__ int   s_ovfn;

    const int g    = blockIdx.x;
    const int tid  = threadIdx.x;
    const int wid  = tid >> 5;
    const int lane = tid & 31;

    if (tid < N_PER) s_cnt[tid] = 0;
    if (tid == 0)    s_ovfn = 0;
    __syncthreads();

    // ---- xw = x @ gcn_w : warp-cooperative, streamed from global (DRAM) ----
    {
        const float4 wv = reinterpret_cast<const float4*>(gcn_w)[lane];
        const float4* xg = reinterpret_cast<const float4*>(x + (size_t)g * N_PER * DD);
        #pragma unroll 4
        for (int i = 0; i < N_PER / 8; ++i) {              // 8 warps, 32 nodes each
            const int node = wid * (N_PER / 8) + i;
            const float4 v = xg[node * (DD / 4) + lane];
            float d = v.x * wv.x + v.y * wv.y + v.z * wv.z + v.w * wv.w;
            #pragma unroll
            for (int off = 16; off; off >>= 1)
                d += __shfl_down_sync(0xFFFFFFFFu, d, off);
            if (lane == 0) s_xwp[node] = d;
        }
    }

    // ---- One-pass bucket scatter: count in-degree AND build CSR buckets ----
    {
        const int4* s4 = reinterpret_cast<const int4*>(edge_index + (size_t)g * E_PER);
        const int4* d4 = reinterpret_cast<const int4*>(edge_index + (size_t)E_total + (size_t)g * E_PER);
        #pragma unroll
        for (int i = tid; i < E_PER / 4; i += T1) {
            const int4 ss = s4[i];
            const int4 dd = d4[i];
            #pragma unroll
            for (int e = 0; e < 4; ++e) {
                const int a = ((&ss.x)[e]) & (N_PER - 1);
                const int b = ((&dd.x)[e]) & (N_PER - 1);
                const int pos = atomicAdd(&s_cnt[b], 1);
                if (pos < MAXB) {
                    s_bkt[b * BSTR + pos] = (unsigned short)a;
                } else {
                    const int k = atomicAdd(&s_ovfn, 1);
                    if (k < OVF_CAP) s_ovf[k] = (b << 16) | a;
                }
            }
        }
    }
    __syncthreads();

    // ---- dinv; pre-scale xwp = xw * dinv ----
    if (tid < N_PER) {
        const float dv = rsqrtf((float)(s_cnt[tid] + 1));  // +1 self-loop
        s_dinv[tid] = dv;
        s_xwp[tid] *= dv;
    }
    __syncthreads();

    // ---- Atomic-free gather: agg_raw[t] = sum of xwp over in-edges ----
    if (tid < N_PER) {
        const int m = min(s_cnt[tid], MAXB);
        const unsigned short* bp = s_bkt + tid * BSTR;
        float sum = 0.0f;
        for (int j = 0; j < m; ++j)
            sum += s_xwp[bp[j]];
        s_agg[tid] = sum;
    }
    __syncthreads();

    // ---- Rare overflow edges (degree > MAXB) via atomics ----
    {
        const int n = min(s_ovfn, OVF_CAP);
        for (int i = tid; i < n; i += T1) {
            const int e = s_ovf[i];
            atomicAdd(&s_agg[e >> 16], s_xwp[e & 0xFFFF]);
        }
    }
    __syncthreads();

    // ---- score + gate ----
    const float bias0 = __ldg(gcn_b);
    if (tid < N_PER) {
        const float sc = s_dinv[tid] * (s_agg[tid] + s_xwp[tid]) + bias0;
        s_agg[tid]  = sc;
        s_gate[tid] = tanhf(sc);
    }
    __syncthreads();

    // ---- top-K by rank counting (stable, matches lax.top_k tie-break) ----
    if (tid < N_PER) {
        const float si = s_agg[tid];
        int cnt = 0;
        #pragma unroll 8
        for (int j = 0; j < N_PER; ++j) {
            const float sj = s_agg[j];
            cnt += (sj > si) || (sj == si && j < tid);
        }
        s_flag[tid] = (cnt < KK) ? 1 : 0;
    }
    __syncthreads();

    // ---- gated mean/max pooling (float4, 8-way node split); x from L2 ----
    {
        const int q  = tid >> 5;           // 0..7
        const int d4 = tid & 31;           // float4 lane -> covers 128 floats
        const float4* xr = reinterpret_cast<const float4*>(x + (size_t)g * N_PER * DD) + d4;
        float4 sum = make_float4(0.f, 0.f, 0.f, 0.f);
        float4 mx  = make_float4(-CUDART_INF_F, -CUDART_INF_F, -CUDART_INF_F, -CUDART_INF_F);
        #pragma unroll 4
        for (int n = q; n < N_PER; n += 8) {
            if (s_flag[n]) {
                const float gt = s_gate[n];
                const float4 v = xr[n * (DD / 4)];
                const float vx = v.x * gt, vy = v.y * gt, vz = v.z * gt, vw = v.w * gt;
                sum.x += vx; sum.y += vy; sum.z += vz; sum.w += vw;
                mx.x = fmaxf(mx.x, vx); mx.y = fmaxf(mx.y, vy);
                mx.z = fmaxf(mx.z, vz); mx.w = fmaxf(mx.w, vw);
            }
        }
        s_psum4[q][d4] = sum;
        s_pmax4[q][d4] = mx;
    }
    __syncthreads();

    // ---- reduce pooling partials into readout [mean | max] ----
    if (tid < 32) {
        float4 a = s_psum4[0][tid];
        #pragma unroll
        for (int q = 1; q < 8; ++q) {
            const float4 b = s_psum4[q][tid];
            a.x += b.x; a.y += b.y; a.z += b.z; a.w += b.w;
        }
        const float inv = 1.0f / (float)KK;
        a.x *= inv; a.y *= inv; a.z *= inv; a.w *= inv;
        reinterpret_cast<float4*>(s_read)[tid] = a;
    } else if (tid < 64) {
        const int t = tid - 32;
        float4 a = s_pmax4[0][t];
        #pragma unroll
        for (int q = 1; q < 8; ++q) {
            const float4 b = s_pmax4[q][t];
            a.x = fmaxf(a.x, b.x); a.y = fmaxf(a.y, b.y);
            a.z = fmaxf(a.z, b.z); a.w = fmaxf(a.w, b.w);
        }
        reinterpret_cast<float4*>(s_read + DD)[t] = a;
    }
    __syncthreads();

    // ---- fused linear epilogue: out[g,:] = readout @ lin_w + lin_b ----
    {
        const int d = tid & (DD - 1);
        const int h = tid >> 7;
        const float* wp = lin_w + h * DD * DD + d;
        const float* rp = s_read + h * DD;
        float acc = 0.0f;
        #pragma unroll 8
        for (int k = 0; k < DD; ++k)
            acc = fmaf(rp[k], __ldg(wp + k * DD), acc);
        if (h == 1) s_part[d] = acc;
        __syncthreads();
        if (h == 0)
            out[g * DD + d] = acc + s_part[d] + __ldg(lin_b + d);
    }
}

// ---------------------------------------------------------------------------
extern "C" void kernel_launch(void* const* d_in, const int* in_sizes, int n_in,
                              void* d_out, int out_size)
{
    const float* x     = (const float*)d_in[0];  // [N, D]
    // d_in[1] = graph_indicator (unused; equal-size contiguous graphs)
    const int*   ei    = (const int*)  d_in[2];  // [2, E]
    const float* gcn_w = (const float*)d_in[3];  // [D, 1]
    const float* gcn_b = (const float*)d_in[4];  // [1]
    const float* lin_w = (const float*)d_in[5];  // [2D, D]
    const float* lin_b = (const float*)d_in[6];  // [D]
    float*       out   = (float*)d_out;          // [G, D]

    const int E_total = in_sizes[2] / 2;

    sagpool_fused_kernel<<<NG, T1>>>(x, ei, gcn_w, gcn_b, lin_w, lin_b, out, E_total);
}

// round 6
// speedup vs baseline: 1.7859x; 1.0625x over previous
#include <cuda_runtime.h>
#include <math_constants.h>

// Problem constants (fixed by the dataset)
#define NG      512     // graphs
#define N_PER   256     // nodes per graph
#define DD      128     // embed dim
#define E_PER   4096    // edges per graph
#define KK      128     // kept nodes per graph
#define T1      256     // threads per CTA
#define MAXB    48      // bucket capacity (max in-degree supported w/o overflow)
#define BSTR    50      // bucket row stride in ushorts (25 words, coprime w/ 32 banks)
#define OVF_CAP 256     // overflow edge list capacity

// ---------------------------------------------------------------------------
// Fully fused: per-graph score -> topk -> compact -> gated mean/max -> linear
// One CTA per graph; 512 CTAs all resident (4/SM). Even/odd CTAs run the two
// independent head phases (x-stream vs edge-scatter) in opposite order so the
// DRAM-heavy and LSU-heavy phases overlap chip-wide.
// ---------------------------------------------------------------------------
__global__ void __launch_bounds__(T1, 4)
sagpool_fused_kernel(const float* __restrict__ x,
                     const int*   __restrict__ edge_index,
                     const float* __restrict__ gcn_w,
                     const float* __restrict__ gcn_b,
                     const float* __restrict__ lin_w,
                     const float* __restrict__ lin_b,
                     float*       __restrict__ out,
                     int E_total)
{
    __shared__ unsigned short s_bkt[N_PER * BSTR];  // 25.6 KB CSR buckets (src ids)
    __shared__ int   s_cnt[N_PER];                  // in-degree / cursor
    __shared__ float s_xwp[N_PER];                  // xw, then xw*dinv
    __shared__ float s_dinv[N_PER];
    __shared__ float s_agg[N_PER];                  // edge sum, then score
    __shared__ float s_gate[N_PER];
    __shared__ unsigned short s_kept[KK];           // compacted kept node ids
    __shared__ int   s_woff[8];                     // per-warp compaction offsets
    __shared__ float4 s_psum4[8][DD / 4];           // 4 KB
    __shared__ float4 s_pmax4[8][DD / 4];           // 4 KB
    __shared__ float s_read[2 * DD];
    __shared__ float s_part[DD];
    __shared__ int   s_ovf[OVF_CAP];                // packed (dst<<16)|src
    __shared__ int   s_ovfn;

    const int g    = blockIdx.x;
    const int tid  = threadIdx.x;
    const int wid  = tid >> 5;
    const int lane = tid & 31;

    if (tid < N_PER) s_cnt[tid] = 0;
    if (tid == 0)    s_ovfn = 0;
    __syncthreads();

    // ---- phase A: xw = x @ gcn_w (warp-cooperative, DRAM stream) ----
    auto do_xw = [&]() {
        const float4 wv = reinterpret_cast<const float4*>(gcn_w)[lane];
        const float4* xg = reinterpret_cast<const float4*>(x + (size_t)g * N_PER * DD);
        #pragma unroll 4
        for (int i = 0; i < N_PER / 8; ++i) {              // 8 warps, 32 nodes each
            const int node = wid * (N_PER / 8) + i;
            const float4 v = xg[node * (DD / 4) + lane];
            float d = v.x * wv.x + v.y * wv.y + v.z * wv.z + v.w * wv.w;
            #pragma unroll
            for (int off = 16; off; off >>= 1)
                d += __shfl_down_sync(0xFFFFFFFFu, d, off);
            if (lane == 0) s_xwp[node] = d;
        }
    };

    // ---- phase B: one-pass bucket scatter (degree + CSR in one atomic) ----
    auto do_scatter = [&]() {
        const int4* s4 = reinterpret_cast<const int4*>(edge_index + (size_t)g * E_PER);
        const int4* d4 = reinterpret_cast<const int4*>(edge_index + (size_t)E_total + (size_t)g * E_PER);
        #pragma unroll
        for (int i = tid; i < E_PER / 4; i += T1) {
            const int4 ss = s4[i];
            const int4 dd = d4[i];
            #pragma unroll
            for (int e = 0; e < 4; ++e) {
                const int a = ((&ss.x)[e]) & (N_PER - 1);
                const int b = ((&dd.x)[e]) & (N_PER - 1);
                const int pos = atomicAdd(&s_cnt[b], 1);
                if (pos < MAXB) {
                    s_bkt[b * BSTR + pos] = (unsigned short)a;
                } else {
                    const int k = atomicAdd(&s_ovfn, 1);
                    if (k < OVF_CAP) s_ovf[k] = (b << 16) | a;
                }
            }
        }
    };

    // Stagger: even CTAs stream x first; odd CTAs scatter edges first.
    if ((g & 1) == 0) { do_xw(); do_scatter(); }
    else              { do_scatter(); do_xw(); }
    __syncthreads();

    // ---- dinv; pre-scale xwp = xw * dinv ----
    if (tid < N_PER) {
        const float dv = rsqrtf((float)(s_cnt[tid] + 1));  // +1 self-loop
        s_dinv[tid] = dv;
        s_xwp[tid] *= dv;
    }
    __syncthreads();

    // ---- Atomic-free gather: agg_raw[t] = sum of xwp over in-edges ----
    if (tid < N_PER) {
        const int m = min(s_cnt[tid], MAXB);
        const unsigned short* bp = s_bkt + tid * BSTR;
        float sum = 0.0f;
        #pragma unroll 2
        for (int j = 0; j < m; ++j)
            sum += s_xwp[bp[j]];
        s_agg[tid] = sum;
    }
    __syncthreads();

    // ---- Rare overflow edges (degree > MAXB) via atomics ----
    {
        const int n = min(s_ovfn, OVF_CAP);
        for (int i = tid; i < n; i += T1) {
            const int e = s_ovf[i];
            atomicAdd(&s_agg[e >> 16], s_xwp[e & 0xFFFF]);
        }
    }
    __syncthreads();

    // ---- score + gate ----
    const float bias0 = __ldg(gcn_b);
    if (tid < N_PER) {
        const float sc = s_dinv[tid] * (s_agg[tid] + s_xwp[tid]) + bias0;
        s_agg[tid]  = sc;
        s_gate[tid] = tanhf(sc);
    }
    __syncthreads();

    // ---- top-K rank counting + in-warp compaction of kept node ids ----
    {
        const float si = s_agg[tid];
        int cnt = 0;
        #pragma unroll 8
        for (int j = 0; j < N_PER; ++j) {
            const float sj = s_agg[j];
            cnt += (sj > si) || (sj == si && j < tid);
        }
        const int keep = (cnt < KK) ? 1 : 0;
        const unsigned ball = __ballot_sync(0xFFFFFFFFu, keep);
        if (lane == 0) s_woff[wid] = __popc(ball);
        __syncthreads();
        if (tid == 0) {                         // tiny serial scan over 8 warps
            int acc = 0;
            #pragma unroll
            for (int w = 0; w < 8; ++w) { const int c = s_woff[w]; s_woff[w] = acc; acc += c; }
        }
        __syncthreads();
        if (keep) {
            const int pos = s_woff[wid] + __popc(ball & ((1u << lane) - 1u));
            s_kept[pos] = (unsigned short)tid;
        }
    }
    __syncthreads();

    // ---- gated mean/max pooling over the 128 kept rows only (L2 re-read) ----
    {
        const int q  = tid >> 5;           // 0..7 : warp id
        const int d4 = tid & 31;           // float4 lane -> covers 128 floats
        const float4* xb = reinterpret_cast<const float4*>(x + (size_t)g * N_PER * DD) + d4;
        float4 sum = make_float4(0.f, 0.f, 0.f, 0.f);
        float4 mx  = make_float4(-CUDART_INF_F, -CUDART_INF_F, -CUDART_INF_F, -CUDART_INF_F);
        #pragma unroll 4
        for (int j = 0; j < KK / 8; ++j) {      // 16 kept nodes per warp
            const int n = s_kept[q * (KK / 8) + j];
            const float gt = s_gate[n];
            const float4 v = xb[n * (DD / 4)];
            const float vx = v.x * gt, vy = v.y * gt, vz = v.z * gt, vw = v.w * gt;
            sum.x += vx; sum.y += vy; sum.z += vz; sum.w += vw;
            mx.x = fmaxf(mx.x, vx); mx.y = fmaxf(mx.y, vy);
            mx.z = fmaxf(mx.z, vz); mx.w = fmaxf(mx.w, vw);
        }
        s_psum4[q][d4] = sum;
        s_pmax4[q][d4] = mx;
    }
    __syncthreads();

    // ---- reduce pooling partials into readout [mean | max] ----
    if (tid < 32) {
        float4 a = s_psum4[0][tid];
        #pragma unroll
        for (int q = 1; q < 8; ++q) {
            const float4 b = s_psum4[q][tid];
            a.x += b.x; a.y += b.y; a.z += b.z; a.w += b.w;
        }
        const float inv = 1.0f / (float)KK;
        a.x *= inv; a.y *= inv; a.z *= inv; a.w *= inv;
        reinterpret_cast<float4*>(s_read)[tid] = a;
    } else if (tid < 64) {
        const int t = tid - 32;
        float4 a = s_pmax4[0][t];
        #pragma unroll
        for (int q = 1; q < 8; ++q) {
            const float4 b = s_pmax4[q][t];
            a.x = fmaxf(a.x, b.x); a.y = fmaxf(a.y, b.y);
            a.z = fmaxf(a.z, b.z); a.w = fmaxf(a.w, b.w);
        }
        reinterpret_cast<float4*>(s_read + DD)[t] = a;
    }
    __syncthreads();

    // ---- fused linear epilogue: out[g,:] = readout @ lin_w + lin_b ----
    {
        const int d = tid & (DD - 1);
        const int h = tid >> 7;
        const float* wp = lin_w + h * DD * DD + d;
        const float* rp = s_read + h * DD;
        float acc = 0.0f;
        #pragma unroll 8
        for (int k = 0; k < DD; ++k)
            acc = fmaf(rp[k], __ldg(wp + k * DD), acc);
        if (h == 1) s_part[d] = acc;
        __syncthreads();
        if (h == 0)
            out[g * DD + d] = acc + s_part[d] + __ldg(lin_b + d);
    }
}

// ---------------------------------------------------------------------------
extern "C" void kernel_launch(void* const* d_in, const int* in_sizes, int n_in,
                              void* d_out, int out_size)
{
    const float* x     = (const float*)d_in[0];  // [N, D]
    // d_in[1] = graph_indicator (unused; equal-size contiguous graphs)
    const int*   ei    = (const int*)  d_in[2];  // [2, E]
    const float* gcn_w = (const float*)d_in[3];  // [D, 1]
    const float* gcn_b = (const float*)d_in[4];  // [1]
    const float* lin_w = (const float*)d_in[5];  // [2D, D]
    const float* lin_b = (const float*)d_in[6];  // [D]
    float*       out   = (float*)d_out;          // [G, D]

    const int E_total = in_sizes[2] / 2;

    sagpool_fused_kernel<<<NG, T1>>>(x, ei, gcn_w, gcn_b, lin_w, lin_b, out, E_total);
}

// round 7
// speedup vs baseline: 2.2035x; 1.2339x over previous
#include <cuda_runtime.h>
#include <math_constants.h>

// Problem constants (fixed by the dataset)
#define NG      512     // graphs
#define N_PER   256     // nodes per graph
#define DD      128     // embed dim
#define E_PER   4096    // edges per graph
#define KK      128     // kept nodes per graph
#define T1      256     // threads per CTA
#define MAXB    48      // bucket capacity (max in-degree supported w/o overflow)
#define BSTR    50      // bucket row stride in ushorts (25 words, coprime w/ 32 banks)
#define OVF_CAP 256     // overflow edge list capacity

// Warp-0 helper: given hist[256], find bucket b* and residual r such that
// suffix(b*+1) < target <= suffix(b*);  r = target - suffix(b*+1).
__device__ __forceinline__ void radix_scan256(const int* hist, int target,
                                              int* out_b, int* out_r, int lane)
{
    int s = 0;
    #pragma unroll
    for (int j = 0; j < 8; ++j) s += hist[lane * 8 + j];
    int suf = s;                                    // inclusive suffix over chunks
    #pragma unroll
    for (int off = 1; off < 32; off <<= 1) {
        const int v = __shfl_down_sync(0xFFFFFFFFu, suf, off);
        if (lane + off < 32) suf += v;
    }
    int suf_next = __shfl_down_sync(0xFFFFFFFFu, suf, 1);
    if (lane == 31) suf_next = 0;
    if (suf_next < target && target <= suf) {       // exactly one lane
        int cumAbove = suf_next;
        #pragma unroll
        for (int j = 7; j >= 0; --j) {
            const int h = hist[lane * 8 + j];
            if (cumAbove < target && target <= cumAbove + h) {
                *out_b = lane * 8 + j;
                *out_r = target - cumAbove;
                break;
            }
            cumAbove += h;
        }
    }
}

// ---------------------------------------------------------------------------
// Fully fused: per-graph score -> radix topk -> compact -> mean/max -> linear
// ---------------------------------------------------------------------------
__global__ void __launch_bounds__(T1, 4)
sagpool_fused_kernel(const float* __restrict__ x,
                     const int*   __restrict__ edge_index,
                     const float* __restrict__ gcn_w,
                     const float* __restrict__ gcn_b,
                     const float* __restrict__ lin_w,
                     const float* __restrict__ lin_b,
                     float*       __restrict__ out,
                     int E_total)
{
    __shared__ unsigned short s_bkt[N_PER * BSTR];  // 25.6 KB CSR buckets (src ids)
    __shared__ int   s_cnt[N_PER];                  // in-degree / cursor / histogram
    __shared__ float s_xwp[N_PER];                  // xw, then xw*dinv
    __shared__ float s_dinv[N_PER];
    __shared__ float s_agg[N_PER];                  // edge sum, then score
    __shared__ float s_gate[N_PER];
    __shared__ unsigned int   s_m[N_PER];           // sortable score keys
    __shared__ unsigned short s_cand[N_PER];        // boundary candidates
    __shared__ unsigned short s_kept[KK];           // compacted kept node ids
    __shared__ int   s_woff[8];                     // per-warp compaction offsets
    __shared__ int   s_sel[5];                      // b1, r1, b2, r2, c2n
    __shared__ float4 s_psum4[8][DD / 4];           // 4 KB
    __shared__ float4 s_pmax4[8][DD / 4];           // 4 KB
    __shared__ float s_read[2 * DD];
    __shared__ float s_part[DD];
    __shared__ int   s_ovf[OVF_CAP];                // packed (dst<<16)|src
    __shared__ int   s_ovfn;

    const int g    = blockIdx.x;
    const int tid  = threadIdx.x;
    const int wid  = tid >> 5;
    const int lane = tid & 31;

    s_cnt[tid] = 0;
    if (tid == 0) s_ovfn = 0;
    __syncthreads();

    // ---- phase A: xw = x @ gcn_w (warp-cooperative, DRAM stream) ----
    auto do_xw = [&]() {
        const float4 wv = reinterpret_cast<const float4*>(gcn_w)[lane];
        const float4* xg = reinterpret_cast<const float4*>(x + (size_t)g * N_PER * DD);
        #pragma unroll 4
        for (int i = 0; i < N_PER / 8; ++i) {              // 8 warps, 32 nodes each
            const int node = wid * (N_PER / 8) + i;
            const float4 v = xg[node * (DD / 4) + lane];
            float d = v.x * wv.x + v.y * wv.y + v.z * wv.z + v.w * wv.w;
            #pragma unroll
            for (int off = 16; off; off >>= 1)
                d += __shfl_down_sync(0xFFFFFFFFu, d, off);
            if (lane == 0) s_xwp[node] = d;
        }
    };

    // ---- phase B: one-pass bucket scatter (degree + CSR in one atomic) ----
    auto do_scatter = [&]() {
        const int4* s4 = reinterpret_cast<const int4*>(edge_index + (size_t)g * E_PER);
        const int4* d4 = reinterpret_cast<const int4*>(edge_index + (size_t)E_total + (size_t)g * E_PER);
        #pragma unroll
        for (int i = tid; i < E_PER / 4; i += T1) {
            const int4 ss = s4[i];
            const int4 dd = d4[i];
            #pragma unroll
            for (int e = 0; e < 4; ++e) {
                const int a = ((&ss.x)[e]) & (N_PER - 1);
                const int b = ((&dd.x)[e]) & (N_PER - 1);
                const int pos = atomicAdd(&s_cnt[b], 1);
                if (pos < MAXB) {
                    s_bkt[b * BSTR + pos] = (unsigned short)a;
                } else {
                    const int k = atomicAdd(&s_ovfn, 1);
                    if (k < OVF_CAP) s_ovf[k] = (b << 16) | a;
                }
            }
        }
    };

    // Stagger: even CTAs stream x first; odd CTAs scatter edges first.
    if ((g & 1) == 0) { do_xw(); do_scatter(); }
    else              { do_scatter(); do_xw(); }
    __syncthreads();

    // ---- dinv; pre-scale xwp = xw * dinv ----
    {
        const float dv = rsqrtf((float)(s_cnt[tid] + 1));  // +1 self-loop
        s_dinv[tid] = dv;
        s_xwp[tid] *= dv;
    }
    __syncthreads();

    // ---- Atomic-free gather: agg_raw[t] = sum of xwp over in-edges ----
    {
        const int m = min(s_cnt[tid], MAXB);
        const unsigned short* bp = s_bkt + tid * BSTR;
        float sum = 0.0f;
        #pragma unroll 2
        for (int j = 0; j < m; ++j)
            sum += s_xwp[bp[j]];
        s_agg[tid] = sum;
    }
    __syncthreads();

    // ---- Rare overflow edges (degree > MAXB) via atomics ----
    {
        const int n = min(s_ovfn, OVF_CAP);
        for (int i = tid; i < n; i += T1) {
            const int e = s_ovf[i];
            atomicAdd(&s_agg[e >> 16], s_xwp[e & 0xFFFF]);
        }
    }
    __syncthreads();

    // ---- score + gate + sortable key ----
    unsigned int ub;
    {
        const float sc = s_dinv[tid] * (s_agg[tid] + s_xwp[tid]) + __ldg(gcn_b);
        s_gate[tid] = tanhf(sc);
        unsigned int u = __float_as_uint(sc);
        ub = (u & 0x80000000u) ? ~u : (u | 0x80000000u);   // monotone map
        s_m[tid] = ub;
    }

    // ---- radix-select top-K: pass 1 (byte 1) ----
    s_cnt[tid] = 0;
    __syncthreads();
    atomicAdd(&s_cnt[ub >> 24], 1);
    __syncthreads();
    if (wid == 0) radix_scan256(s_cnt, KK, &s_sel[0], &s_sel[1], lane);
    __syncthreads();
    const int b1 = s_sel[0], r1 = s_sel[1];
    const int byte1 = (int)(ub >> 24);
    bool keep = (byte1 > b1);
    const bool cand1 = (byte1 == b1);

    // ---- pass 2 (byte 2) among boundary bucket ----
    s_cnt[tid] = 0;
    __syncthreads();
    if (cand1) atomicAdd(&s_cnt[(ub >> 16) & 255], 1);
    __syncthreads();
    if (wid == 0) radix_scan256(s_cnt, r1, &s_sel[2], &s_sel[3], lane);
    __syncthreads();
    const int b2 = s_sel[2], r2 = s_sel[3];
    const int byte2 = (int)((ub >> 16) & 255);
    keep = keep || (cand1 && byte2 > b2);
    const bool cand2 = cand1 && (byte2 == b2);

    // ---- exact stable rank among the (tiny) final candidate set ----
    {
        const unsigned ball = __ballot_sync(0xFFFFFFFFu, cand2);
        if (lane == 0) s_woff[wid] = __popc(ball);
        __syncthreads();
        if (tid == 0) {
            int acc = 0;
            #pragma unroll
            for (int w = 0; w < 8; ++w) { const int c = s_woff[w]; s_woff[w] = acc; acc += c; }
            s_sel[4] = acc;
        }
        __syncthreads();
        if (cand2) {
            const int pos = s_woff[wid] + __popc(ball & ((1u << lane) - 1u));
            s_cand[pos] = (unsigned short)tid;
        }
        __syncthreads();
        if (cand2) {
            const int c = s_sel[4];
            int rank = 0;
            for (int j = 0; j < c; ++j) {
                const int idx = s_cand[j];
                const unsigned int mj = s_m[idx];
                rank += (mj > ub) || (mj == ub && idx < tid);
            }
            keep = (rank < r2);
        }
    }
    __syncthreads();

    // ---- compact kept node ids (exactly KK of them) ----
    {
        const unsigned ball = __ballot_sync(0xFFFFFFFFu, keep);
        if (lane == 0) s_woff[wid] = __popc(ball);
        __syncthreads();
        if (tid == 0) {
            int acc = 0;
            #pragma unroll
            for (int w = 0; w < 8; ++w) { const int c = s_woff[w]; s_woff[w] = acc; acc += c; }
        }
        __syncthreads();
        if (keep) {
            const int pos = s_woff[wid] + __popc(ball & ((1u << lane) - 1u));
            s_kept[pos] = (unsigned short)tid;
        }
    }
    __syncthreads();

    // ---- gated mean/max pooling over the 128 kept rows only (L2 re-read) ----
    {
        const int q  = tid >> 5;           // 0..7 : warp id
        const int d4 = tid & 31;           // float4 lane -> covers 128 floats
        const float4* xb = reinterpret_cast<const float4*>(x + (size_t)g * N_PER * DD) + d4;
        float4 sum = make_float4(0.f, 0.f, 0.f, 0.f);
        float4 mx  = make_float4(-CUDART_INF_F, -CUDART_INF_F, -CUDART_INF_F, -CUDART_INF_F);
        #pragma unroll 4
        for (int j = 0; j < KK / 8; ++j) {      // 16 kept nodes per warp
            const int n = s_kept[q * (KK / 8) + j];
            const float gt = s_gate[n];
            const float4 v = xb[n * (DD / 4)];
            const float vx = v.x * gt, vy = v.y * gt, vz = v.z * gt, vw = v.w * gt;
            sum.x += vx; sum.y += vy; sum.z += vz; sum.w += vw;
            mx.x = fmaxf(mx.x, vx); mx.y = fmaxf(mx.y, vy);
            mx.z = fmaxf(mx.z, vz); mx.w = fmaxf(mx.w, vw);
        }
        s_psum4[q][d4] = sum;
        s_pmax4[q][d4] = mx;
    }
    __syncthreads();

    // ---- reduce pooling partials into readout [mean | max] ----
    if (tid < 32) {
        float4 a = s_psum4[0][tid];
        #pragma unroll
        for (int q = 1; q < 8; ++q) {
            const float4 b = s_psum4[q][tid];
            a.x += b.x; a.y += b.y; a.z += b.z; a.w += b.w;
        }
        const float inv = 1.0f / (float)KK;
        a.x *= inv; a.y *= inv; a.z *= inv; a.w *= inv;
        reinterpret_cast<float4*>(s_read)[tid] = a;
    } else if (tid < 64) {
        const int t = tid - 32;
        float4 a = s_pmax4[0][t];
        #pragma unroll
        for (int q = 1; q < 8; ++q) {
            const float4 b = s_pmax4[q][t];
            a.x = fmaxf(a.x, b.x); a.y = fmaxf(a.y, b.y);
            a.z = fmaxf(a.z, b.z); a.w = fmaxf(a.w, b.w);
        }
        reinterpret_cast<float4*>(s_read + DD)[t] = a;
    }
    __syncthreads();

    // ---- fused linear epilogue: out[g,:] = readout @ lin_w + lin_b ----
    {
        const int d = tid & (DD - 1);
        const int h = tid >> 7;
        const float* wp = lin_w + h * DD * DD + d;
        const float* rp = s_read + h * DD;
        float acc = 0.0f;
        #pragma unroll 8
        for (int k = 0; k < DD; ++k)
            acc = fmaf(rp[k], __ldg(wp + k * DD), acc);
        if (h == 1) s_part[d] = acc;
        __syncthreads();
        if (h == 0)
            out[g * DD + d] = acc + s_part[d] + __ldg(lin_b + d);
    }
}

// ---------------------------------------------------------------------------
extern "C" void kernel_launch(void* const* d_in, const int* in_sizes, int n_in,
                              void* d_out, int out_size)
{
    const float* x     = (const float*)d_in[0];  // [N, D]
    // d_in[1] = graph_indicator (unused; equal-size contiguous graphs)
    const int*   ei    = (const int*)  d_in[2];  // [2, E]
    const float* gcn_w = (const float*)d_in[3];  // [D, 1]
    const float* gcn_b = (const float*)d_in[4];  // [1]
    const float* lin_w = (const float*)d_in[5];  // [2D, D]
    const float* lin_b = (const float*)d_in[6];  // [D]
    float*       out   = (float*)d_out;          // [G, D]

    const int E_total = in_sizes[2] / 2;

    sagpool_fused_kernel<<<NG, T1>>>(x, ei, gcn_w, gcn_b, lin_w, lin_b, out, E_total);
}